// round 8
// baseline (speedup 1.0000x reference)
#include <cuda_runtime.h>

#define NN   3072
#define EE   3072
#define ELG  6144
#define FF   64
#define HH   4
#define RPH  768        // input rows per head after .view scramble
#define TABH 9437184    // 3072*3072, lg keys offset by this

// -------- scratch (__device__ globals; no allocations allowed) --------
__device__ float g_NV[NN * 256];
__device__ float g_EV[EE * 256];
__device__ float g_srkp[2 * 48 * 4 * 64];   // partial srk sums [g][chunk][h][f]
__device__ float g_WT[2 * 256 * 64];        // transposed Wq (node, edge)
__device__ float g_att[2 * 4 * 3072];       // g=0: node att, g=1: edge att
__device__ unsigned char g_winN[EE];
__device__ unsigned char g_winL[ELG];
__device__ int g_tab[2 * TABH];             // dedup tournament table (zero invariant)

// packed f32x2 helpers (FFMA2 path — ptxas never emits this from plain C++)
__device__ __forceinline__ unsigned long long pk2(float w) {
    unsigned long long r;
    asm("mov.b64 %0, {%1, %1};" : "=l"(r) : "f"(w));
    return r;
}
__device__ __forceinline__ void ffma2(unsigned long long& d,
                                      unsigned long long a, unsigned long long b) {
    asm("fma.rn.f32x2 %0, %1, %2, %0;" : "+l"(d) : "l"(a), "l"(b));
}
__device__ __forceinline__ void unpk2(unsigned long long v, float& lo, float& hi) {
    asm("mov.b64 {%0, %1}, %2;" : "=f"(lo), "=f"(hi) : "l"(v));
}

// ======================= kernel A: all input-only work =======================
// roles by blockIdx.x:
//   [0,96)      srk partials (fused K projection, never materialized)
//   [96,480)    V gemms: 64x64 tiles, NV (192 blocks), EV (192 blocks)
//   [480,516)   dedup atomicMax tournament (9216 edges)
//   [516,524)   transpose Wq (node 4 tiles, edge 4 tiles)
__global__ void __launch_bounds__(256) kA(
    const float* nin, const float* ein,
    const float* nkW, const float* nkb, const float* ekW, const float* ekb,
    const float* nvW, const float* nvb, const float* evW, const float* evb,
    const float* nqW, const float* eqW,
    const int* src, const int* dst, const int* lgs, const int* lgd)
{
    __shared__ __align__(16) float sm[8512];   // unioned per role (~34KB)
    int b = blockIdx.x, tid = threadIdx.x;

    if (b < 96) {
        // ---- srk role: chunk of 64 nodes (16 KM rows per head) ----
        int g = b / 48, chunk = b % 48;
        const float* in = g ? ein : nin;
        const float* W  = g ? ekW : nkW;
        const float* bk = g ? ekb : nkb;
        float* s_in4 = sm;           // 4 heads * 16 rows * stride 68 = 4352
        float* s_wT  = sm + 4352;    // 4 * 68
        float* s_km  = sm + 4624;    // 4 * 64

        {   // vectorized fill: 256 float4 per head-slice = 1/thread
            const float4* in4g = (const float4*)in;
            int rr = tid >> 4, k4 = tid & 15;
            #pragma unroll
            for (int h2 = 0; h2 < 4; h2++)
                *(float4*)&s_in4[h2 * 1088 + rr * 68 + k4 * 4] =
                    in4g[(h2 * RPH + chunk * 16 + rr) * 16 + k4];
        }
        {   // transpose tiny K weights: s_wT[c][k] = W[k*4+c]
            int k = tid >> 2, c = tid & 3;
            s_wT[c * 68 + k] = W[tid];
        }
        __syncthreads();
        // phase 1: k[h, n] = KM[h*768 + n/4, n%4]
        int h = tid >> 6, idx = tid & 63;
        int rl = idx >> 2, c = idx & 3;
        float acc = bk[c];
        const float4* arow = (const float4*)&s_in4[h * 1088 + rl * 68];
        const float4* wrow = (const float4*)&s_wT[c * 68];
        #pragma unroll
        for (int k4 = 0; k4 < 16; k4++) {
            float4 a = arow[k4], w = wrow[k4];
            acc += a.x * w.x + a.y * w.y + a.z * w.z + a.w * w.w;
        }
        s_km[h * 64 + rl * 4 + c] = acc;   // index == h*64 + local n
        __syncthreads();
        // phase 2: srk partial: srk[h,f] += in[n,f] * k[h,n] over 64 n
        int f = tid & 63;
        float sacc = 0.f;
        int n0 = chunk * 64;
        #pragma unroll 8
        for (int nl = 0; nl < 64; nl++)
            sacc += in[(n0 + nl) * 64 + f] * s_km[h * 64 + nl];
        g_srkp[((g * 48 + chunk) * 4 + h) * 64 + f] = sacc;

    } else if (b < 480) {
        // ---- V gemm role: [3072x64] @ [64x256] + bias, f32x2-packed ----
        int i2 = b - 96;
        int mat = i2 / 192;
        int rem = i2 % 192;
        int r0 = (rem >> 2) * 64, c0 = (rem & 3) * 64;
        const float* in = mat ? ein : nin;
        const float* W  = mat ? evW : nvW;
        const float* bb = mat ? evb : nvb;
        float* outv     = mat ? g_EV : g_NV;
        float* As = sm;                  // 64 k * stride 68 = 4352
        float* Ws = sm + 4352;           // 64*64
        float* Bs = sm + 8448;           // 64

        #pragma unroll
        for (int i = 0; i < 16; i++) {   // A tile, transposed store (k-major)
            int idx = i * 256 + tid;
            int r = idx >> 6, k = idx & 63;
            As[k * 68 + r] = in[r0 * 64 + idx];
        }
        #pragma unroll
        for (int i = 0; i < 4; i++) {    // W tile, vectorized copy
            int idx = i * 256 + tid;
            int k = idx >> 4, c4 = idx & 15;
            *(float4*)&Ws[k * 64 + c4 * 4] =
                *(const float4*)&W[k * 256 + c0 + c4 * 4];
        }
        if (tid < 64) Bs[tid] = bb[c0 + tid];
        __syncthreads();

        int tx = tid & 15, ty = tid >> 4;
        int rl = ty * 4, cl = tx * 4;
        unsigned long long acc2[2][4];   // row-pairs (rl+2p, rl+2p+1) x 4 cols
        #pragma unroll
        for (int j = 0; j < 4; j++) {
            unsigned long long p = pk2(Bs[cl + j]);
            acc2[0][j] = p; acc2[1][j] = p;
        }

        #pragma unroll 16
        for (int k = 0; k < 64; k++) {
            ulonglong2 a = *(const ulonglong2*)&As[k * 68 + rl];
            float4 w = *(const float4*)&Ws[k * 64 + cl];
            unsigned long long wx = pk2(w.x), wy = pk2(w.y),
                               wz = pk2(w.z), ww = pk2(w.w);
            ffma2(acc2[0][0], a.x, wx); ffma2(acc2[1][0], a.y, wx);
            ffma2(acc2[0][1], a.x, wy); ffma2(acc2[1][1], a.y, wy);
            ffma2(acc2[0][2], a.x, wz); ffma2(acc2[1][2], a.y, wz);
            ffma2(acc2[0][3], a.x, ww); ffma2(acc2[1][3], a.y, ww);
        }
        #pragma unroll
        for (int p = 0; p < 2; p++) {
            float lo[4], hi[4];
            #pragma unroll
            for (int j = 0; j < 4; j++) unpk2(acc2[p][j], lo[j], hi[j]);
            *(float4*)&outv[(r0 + rl + 2 * p)     * 256 + c0 + cl] =
                make_float4(lo[0], lo[1], lo[2], lo[3]);
            *(float4*)&outv[(r0 + rl + 2 * p + 1) * 256 + c0 + cl] =
                make_float4(hi[0], hi[1], hi[2], hi[3]);
        }

    } else if (b < 516) {
        // ---- dedup tournament: atomicMax(tab[key], e+1) ----
        int e = (b - 480) * 256 + tid;
        if (e < EE) {
            atomicMax(&g_tab[src[e] * 3072 + dst[e]], e + 1);
        } else {
            int l = e - EE;
            atomicMax(&g_tab[TABH + lgs[l] * 3072 + lgd[l]], l + 1);
        }

    } else {
        // ---- transpose Wq: [64k][256c] -> WT[256c][64k] ----
        int t = b - 516;
        int mat = t >> 2, tile = t & 3;
        const float* W = mat ? eqW : nqW;
        float* s = sm;   // 64*65
        #pragma unroll
        for (int i = 0; i < 16; i++) {
            int idx = i * 256 + tid;
            int k = idx >> 6, c = idx & 63;
            s[k * 65 + c] = W[k * 256 + tile * 64 + c];
        }
        __syncthreads();
        #pragma unroll
        for (int i = 0; i < 16; i++) {
            int idx = i * 256 + tid;
            int c = idx >> 6, k = idx & 63;
            g_WT[mat * 16384 + (tile * 64 + c) * 64 + k] = s[k * 65 + c];
        }
    }
}

// ===== kernel BC: fused srk-reduce + c/d + logits + softmax (blocks 0-7) =====
// blocks 8-16: read dedup winners; blocks 17-112: zero the output buffer.
__global__ void __launch_bounds__(1024) kBC(
    const float* nin, const float* ein, const float* nqb, const float* eqb,
    const int* src, const int* dst, const int* lgs, const int* lgd,
    float* out)
{
    int tid = threadIdx.x;
    if (blockIdx.x >= 17) {
        // zero output: 96 blocks x 1024 float4 = 393216 floats
        int idx = (blockIdx.x - 17) * 1024 + tid;
        ((float4*)out)[idx] = make_float4(0.f, 0.f, 0.f, 0.f);
        return;
    }
    if (blockIdx.x >= 8) {
        int idx = (blockIdx.x - 8) * 1024 + tid;
        if (idx < EE) {
            g_winN[idx] = (g_tab[src[idx] * 3072 + dst[idx]] == idx + 1);
        } else if (idx < EE + ELG) {
            int l = idx - EE;
            g_winL[l] = (g_tab[TABH + lgs[l] * 3072 + lgd[l]] == l + 1);
        }
        return;
    }

    __shared__ __align__(16) float s_buf[2][64 * 68];  // double-buffered staging
    __shared__ float s_srk[64];
    __shared__ __align__(16) float s_c[4 * 68];
    __shared__ float s_d[4];
    __shared__ float s_red[32];
    __shared__ float s_v;

    int g = blockIdx.x >> 2, h = blockIdx.x & 3;
    const float* in = g ? ein : nin;

    // ---- phase 1: reduce srk partials (48 chunks), scratch = s_buf[0] ----
    float* s_part = s_buf[0];
    {
        int f = tid & 63, p = tid >> 6;    // 16 groups x 3 chunks
        float a = 0.f;
        #pragma unroll
        for (int q = 0; q < 3; q++)
            a += g_srkp[((g * 48 + p * 3 + q) * 4 + h) * 64 + f];
        s_part[tid] = a;
    }
    __syncthreads();
    if (tid < 64) {
        float a = 0.f;
        #pragma unroll
        for (int p = 0; p < 16; p++) a += s_part[p * 64 + tid];
        s_srk[tid] = a;
    }
    __syncthreads();

    // ---- phase 2: c[j][k] = sum_f Wq[k,64j+f]*srk[f];  d[j] = bq[j]::srk ----
    if (tid < 256) {
        int j = tid & 3, k = tid >> 2;
        const float* wt = g_WT + g * 16384 + j * 4096;   // WT[(j*64+f)*64 + k]
        float a = 0.f;
        #pragma unroll
        for (int f = 0; f < 64; f++)
            a += wt[f * 64 + k] * s_srk[f];
        s_c[j * 68 + k] = a;
    } else if (tid < 260) {
        int j = tid - 256;
        const float* bq = g ? eqb : nqb;
        float dd = 0.f;
        #pragma unroll
        for (int f = 0; f < 64; f++) dd += bq[j * 64 + f] * s_srk[f];
        s_d[j] = dd;
    }
    __syncthreads();

    // ---- phase 3: logits, double-buffered 64-row chunks ----
    // compute threads (tid<512): ml = row-in-chunk, jj = view col, half = row half
    float x12[12];
    float lmax = -1e30f;
    int ml = tid >> 3, jj = (tid >> 1) & 3, half = tid & 1;
    const float4* in4 = (const float4*)(in + (size_t)(h * RPH) * 64);
    int fr = tid >> 4, fk = tid & 15;       // fill coords: 64 rows x 16 f4 = 1024
    *(float4*)&s_buf[0][fr * 68 + fk * 4] = in4[fr * 16 + fk];
    __syncthreads();
    #pragma unroll
    for (int c = 0; c < 12; c++) {
        int cur = c & 1;
        if (c < 11)
            *(float4*)&s_buf[cur ^ 1][fr * 68 + fk * 4] =
                in4[((c + 1) * 64 + fr) * 16 + fk];
        if (tid < 512) {
            const float4* row = (const float4*)&s_buf[cur][ml * 68 + half * 32];
            const float4* cj  = (const float4*)&s_c[jj * 68 + half * 32];
            float a0 = 0.f, a1 = 0.f, a2 = 0.f, a3 = 0.f;
            #pragma unroll
            for (int k = 0; k < 8; k += 4) {
                float4 r0 = row[k + 0], c0 = cj[k + 0];
                float4 r1 = row[k + 1], c1 = cj[k + 1];
                float4 r2 = row[k + 2], c2 = cj[k + 2];
                float4 r3 = row[k + 3], c3 = cj[k + 3];
                a0 += r0.x * c0.x + r0.y * c0.y + r0.z * c0.z + r0.w * c0.w;
                a1 += r1.x * c1.x + r1.y * c1.y + r1.z * c1.z + r1.w * c1.w;
                a2 += r2.x * c2.x + r2.y * c2.y + r2.z * c2.z + r2.w * c2.w;
                a3 += r3.x * c3.x + r3.y * c3.y + r3.z * c3.z + r3.w * c3.w;
            }
            float part = (a0 + a1) + (a2 + a3);
            float other = __shfl_xor_sync(0xffffffffu, part, 1);
            float x = (s_d[jj] + (part + other)) * 0.125f;
            x12[c] = x;
            lmax = fmaxf(lmax, x);
        }
        __syncthreads();
    }

    // ---- phase 4: softmax over 3072 (x values duplicated across half pair) ----
    #pragma unroll
    for (int o = 16; o > 0; o >>= 1)
        lmax = fmaxf(lmax, __shfl_xor_sync(0xffffffffu, lmax, o));
    if ((tid & 31) == 0) s_red[tid >> 5] = lmax;
    __syncthreads();
    if (tid == 0) {
        float m2 = s_red[0];
        #pragma unroll
        for (int i = 1; i < 32; i++) m2 = fmaxf(m2, s_red[i]);
        s_v = m2;
    }
    __syncthreads();
    float mx = s_v;
    float e12[12];
    float lsum = 0.f;
    if (tid < 512) {
        #pragma unroll
        for (int c = 0; c < 12; c++)
            e12[c] = __expf(x12[c] - mx);
        if (half == 0) {
            #pragma unroll
            for (int c = 0; c < 12; c++) lsum += e12[c];
        }
    }
    #pragma unroll
    for (int o = 16; o > 0; o >>= 1)
        lsum += __shfl_xor_sync(0xffffffffu, lsum, o);
    __syncthreads();
    if ((tid & 31) == 0) s_red[tid >> 5] = lsum;
    __syncthreads();
    if (tid == 0) {
        float s = 0.f;
        #pragma unroll
        for (int i = 0; i < 32; i++) s += s_red[i];
        s_v = 1.f / s;
    }
    __syncthreads();
    float inv = s_v;
    if (tid < 512 && half == 0) {
        float* att = g_att + (g * 4 + h) * 3072;
        #pragma unroll
        for (int c = 0; c < 12; c++)
            att[(c * 64 + ml) * 4 + jj] = e12[c] * inv;
    }
}

// ======= kernel D: message-passing scatter (16 lanes/edge, float4 atomics) =======
// blocks 0-35 also reset the tournament table (nothing reads g_tab this launch)
__global__ void __launch_bounds__(256) kD(
    const int* src, const int* dst, const int* lgs, const int* lgd, float* out)
{
    int tid = threadIdx.x;
    int bx = blockIdx.x;

    if (bx < 36) {
        int e = bx * 256 + tid;
        if (e < EE) g_tab[src[e] * 3072 + dst[e]] = 0;
        else {
            int l = e - EE;
            g_tab[TABH + lgs[l] * 3072 + lgd[l]] = 0;
        }
    }

    int u = tid >> 4;            // 16 edges per block
    int q = (tid & 15) * 4;      // float4 lane within feature dim
    if (bx < 192) {                                    // node messages (edge att, g=1)
        int e = bx * 16 + u;
        if (!g_winN[e]) return;
        int s = src[e], d = dst[e];
        float4 acc = make_float4(0.f, 0.f, 0.f, 0.f);
        #pragma unroll
        for (int h = 0; h < 4; h++) {
            float a = __ldg(&g_att[(4 + h) * 3072 + e]);
            float4 v = *(const float4*)&g_NV[((size_t)(h * 3072 + d)) * 64 + q];
            acc.x += a * v.x; acc.y += a * v.y; acc.z += a * v.z; acc.w += a * v.w;
        }
        acc.x *= 0.25f; acc.y *= 0.25f; acc.z *= 0.25f; acc.w *= 0.25f;
        atomicAdd((float4*)&out[s * 64 + q], acc);     // mean over heads
    } else {                                           // line-graph messages (node att, g=0)
        int l = (bx - 192) * 16 + u;
        if (!g_winL[l]) return;
        int e1 = lgs[l], e2 = lgd[l];
        int c = dst[e1];
        float4 acc = make_float4(0.f, 0.f, 0.f, 0.f);
        #pragma unroll
        for (int h = 0; h < 4; h++) {
            float a = __ldg(&g_att[h * 3072 + c]);
            float4 v = *(const float4*)&g_EV[((size_t)(h * 3072 + e2)) * 64 + q];
            acc.x += a * v.x; acc.y += a * v.y; acc.z += a * v.z; acc.w += a * v.w;
        }
        acc.x *= 0.25f; acc.y *= 0.25f; acc.z *= 0.25f; acc.w *= 0.25f;
        atomicAdd((float4*)&out[NN * 64 + e1 * 64 + q], acc);
    }
}

extern "C" void kernel_launch(void* const* d_in, const int* in_sizes, int n_in,
                              void* d_out, int out_size)
{
    const float* nin = (const float*)d_in[0];
    const float* ein = (const float*)d_in[1];
    const int* src = (const int*)d_in[2];
    const int* dst = (const int*)d_in[3];
    const int* lgs = (const int*)d_in[4];
    const int* lgd = (const int*)d_in[5];
    const float* nqW = (const float*)d_in[6];  const float* nqb = (const float*)d_in[7];
    const float* nkW = (const float*)d_in[8];  const float* nkb = (const float*)d_in[9];
    const float* nvW = (const float*)d_in[10]; const float* nvb = (const float*)d_in[11];
    const float* eqW = (const float*)d_in[12]; const float* eqb = (const float*)d_in[13];
    const float* ekW = (const float*)d_in[14]; const float* ekb = (const float*)d_in[15];
    const float* evW = (const float*)d_in[16]; const float* evb = (const float*)d_in[17];
    float* out = (float*)d_out;

    kA<<<524, 256>>>(nin, ein, nkW, nkb, ekW, ekb, nvW, nvb, evW, evb,
                     nqW, eqW, src, dst, lgs, lgd);
    kBC<<<113, 1024>>>(nin, ein, nqb, eqb, src, dst, lgs, lgd, out);
    kD<<<576, 256>>>(src, dst, lgs, lgd, out);
}

// round 9
// speedup vs baseline: 1.2028x; 1.2028x over previous
#include <cuda_runtime.h>

#define NN   3072
#define EE   3072
#define ELG  6144
#define FF   64
#define HH   4
#define RPH  768        // input rows per head after .view scramble
#define TABH 9437184    // 3072*3072, lg keys offset by this

// -------- scratch (__device__ globals; no allocations allowed) --------
__device__ float g_NV[NN * 256];
__device__ float g_EV[EE * 256];
__device__ float g_srkp[2 * 48 * 4 * 64];   // partial srk sums [g][chunk][h][f]
__device__ float g_WT[2 * 256 * 64];        // transposed Wq (node, edge)
__device__ float g_att[2 * 4 * 3072];       // g=0: node att, g=1: edge att
__device__ unsigned char g_winN[EE];
__device__ unsigned char g_winL[ELG];
__device__ int g_tab[2 * TABH];             // dedup tournament table (zero invariant)

// packed f32x2 helpers (FFMA2 path — ptxas never emits this from plain C++)
__device__ __forceinline__ unsigned long long pk2(float w) {
    unsigned long long r;
    asm("mov.b64 %0, {%1, %1};" : "=l"(r) : "f"(w));
    return r;
}
__device__ __forceinline__ void ffma2(unsigned long long& d,
                                      unsigned long long a, unsigned long long b) {
    asm("fma.rn.f32x2 %0, %1, %2, %0;" : "+l"(d) : "l"(a), "l"(b));
}
__device__ __forceinline__ void unpk2(unsigned long long v, float& lo, float& hi) {
    asm("mov.b64 {%0, %1}, %2;" : "=f"(lo), "=f"(hi) : "l"(v));
}

// ======================= kernel A: all input-only work =======================
// roles by blockIdx.x:
//   [0,96)      srk partials (fused K projection, never materialized)
//   [96,480)    V gemms: 64x64 tiles, NV (192 blocks), EV (192 blocks)
//   [480,516)   dedup atomicMax tournament (9216 edges)
//   [516,524)   transpose Wq (node 4 tiles, edge 4 tiles)
__global__ void __launch_bounds__(256) kA(
    const float* nin, const float* ein,
    const float* nkW, const float* nkb, const float* ekW, const float* ekb,
    const float* nvW, const float* nvb, const float* evW, const float* evb,
    const float* nqW, const float* eqW,
    const int* src, const int* dst, const int* lgs, const int* lgd)
{
    __shared__ __align__(16) float sm[8512];   // unioned per role (~34KB)
    int b = blockIdx.x, tid = threadIdx.x;

    if (b < 96) {
        // ---- srk role: chunk of 64 nodes (16 KM rows per head) ----
        int g = b / 48, chunk = b % 48;
        const float* in = g ? ein : nin;
        const float* W  = g ? ekW : nkW;
        const float* bk = g ? ekb : nkb;
        float* s_in4 = sm;           // 4 heads * 16 rows * stride 68 = 4352
        float* s_wT  = sm + 4352;    // 4 * 68
        float* s_km  = sm + 4624;    // 4 * 64

        {   // vectorized fill: 256 float4 per head-slice = 1/thread
            const float4* in4g = (const float4*)in;
            int rr = tid >> 4, k4 = tid & 15;
            #pragma unroll
            for (int h2 = 0; h2 < 4; h2++)
                *(float4*)&s_in4[h2 * 1088 + rr * 68 + k4 * 4] =
                    in4g[(h2 * RPH + chunk * 16 + rr) * 16 + k4];
        }
        {   // transpose tiny K weights: s_wT[c][k] = W[k*4+c]
            int k = tid >> 2, c = tid & 3;
            s_wT[c * 68 + k] = W[tid];
        }
        __syncthreads();
        // phase 1: k[h, n] = KM[h*768 + n/4, n%4]
        int h = tid >> 6, idx = tid & 63;
        int rl = idx >> 2, c = idx & 3;
        float acc = bk[c];
        const float4* arow = (const float4*)&s_in4[h * 1088 + rl * 68];
        const float4* wrow = (const float4*)&s_wT[c * 68];
        #pragma unroll
        for (int k4 = 0; k4 < 16; k4++) {
            float4 a = arow[k4], w = wrow[k4];
            acc += a.x * w.x + a.y * w.y + a.z * w.z + a.w * w.w;
        }
        s_km[h * 64 + rl * 4 + c] = acc;   // index == h*64 + local n
        __syncthreads();
        // phase 2: srk partial: srk[h,f] += in[n,f] * k[h,n] over 64 n
        int f = tid & 63;
        float sacc = 0.f;
        int n0 = chunk * 64;
        #pragma unroll 8
        for (int nl = 0; nl < 64; nl++)
            sacc += in[(n0 + nl) * 64 + f] * s_km[h * 64 + nl];
        g_srkp[((g * 48 + chunk) * 4 + h) * 64 + f] = sacc;

    } else if (b < 480) {
        // ---- V gemm role: [3072x64] @ [64x256] + bias, f32x2-packed ----
        int i2 = b - 96;
        int mat = i2 / 192;
        int rem = i2 % 192;
        int r0 = (rem >> 2) * 64, c0 = (rem & 3) * 64;
        const float* in = mat ? ein : nin;
        const float* W  = mat ? evW : nvW;
        const float* bb = mat ? evb : nvb;
        float* outv     = mat ? g_EV : g_NV;
        float* As = sm;                  // 64 k * stride 68 = 4352
        float* Ws = sm + 4352;           // 64*64
        float* Bs = sm + 8448;           // 64

        #pragma unroll
        for (int i = 0; i < 16; i++) {   // A tile, transposed store (k-major)
            int idx = i * 256 + tid;
            int r = idx >> 6, k = idx & 63;
            As[k * 68 + r] = in[r0 * 64 + idx];
        }
        #pragma unroll
        for (int i = 0; i < 4; i++) {    // W tile, vectorized copy
            int idx = i * 256 + tid;
            int k = idx >> 4, c4 = idx & 15;
            *(float4*)&Ws[k * 64 + c4 * 4] =
                *(const float4*)&W[k * 256 + c0 + c4 * 4];
        }
        if (tid < 64) Bs[tid] = bb[c0 + tid];
        __syncthreads();

        int tx = tid & 15, ty = tid >> 4;
        int rl = ty * 4, cl = tx * 4;
        unsigned long long acc2[2][4];   // row-pairs (rl+2p, rl+2p+1) x 4 cols
        #pragma unroll
        for (int j = 0; j < 4; j++) {
            unsigned long long p = pk2(Bs[cl + j]);
            acc2[0][j] = p; acc2[1][j] = p;
        }

        #pragma unroll 16
        for (int k = 0; k < 64; k++) {
            ulonglong2 a = *(const ulonglong2*)&As[k * 68 + rl];
            float4 w = *(const float4*)&Ws[k * 64 + cl];
            unsigned long long wx = pk2(w.x), wy = pk2(w.y),
                               wz = pk2(w.z), ww = pk2(w.w);
            ffma2(acc2[0][0], a.x, wx); ffma2(acc2[1][0], a.y, wx);
            ffma2(acc2[0][1], a.x, wy); ffma2(acc2[1][1], a.y, wy);
            ffma2(acc2[0][2], a.x, wz); ffma2(acc2[1][2], a.y, wz);
            ffma2(acc2[0][3], a.x, ww); ffma2(acc2[1][3], a.y, ww);
        }
        #pragma unroll
        for (int p = 0; p < 2; p++) {
            float lo[4], hi[4];
            #pragma unroll
            for (int j = 0; j < 4; j++) unpk2(acc2[p][j], lo[j], hi[j]);
            *(float4*)&outv[(r0 + rl + 2 * p)     * 256 + c0 + cl] =
                make_float4(lo[0], lo[1], lo[2], lo[3]);
            *(float4*)&outv[(r0 + rl + 2 * p + 1) * 256 + c0 + cl] =
                make_float4(hi[0], hi[1], hi[2], hi[3]);
        }

    } else if (b < 516) {
        // ---- dedup tournament: atomicMax(tab[key], e+1) ----
        int e = (b - 480) * 256 + tid;
        if (e < EE) {
            atomicMax(&g_tab[src[e] * 3072 + dst[e]], e + 1);
        } else {
            int l = e - EE;
            atomicMax(&g_tab[TABH + lgs[l] * 3072 + lgd[l]], l + 1);
        }

    } else {
        // ---- transpose Wq: [64k][256c] -> WT[256c][64k] ----
        int t = b - 516;
        int mat = t >> 2, tile = t & 3;
        const float* W = mat ? eqW : nqW;
        float* s = sm;   // 64*65
        #pragma unroll
        for (int i = 0; i < 16; i++) {
            int idx = i * 256 + tid;
            int k = idx >> 6, c = idx & 63;
            s[k * 65 + c] = W[k * 256 + tile * 64 + c];
        }
        __syncthreads();
        #pragma unroll
        for (int i = 0; i < 16; i++) {
            int idx = i * 256 + tid;
            int c = idx >> 6, k = idx & 63;
            g_WT[mat * 16384 + (tile * 64 + c) * 64 + k] = s[k * 65 + c];
        }
    }
}

// ===== kernel BC: fused srk-reduce + c/d + logits + softmax (blocks 0-7) =====
// ===== blocks 8-16: read dedup winners from tournament table            =====
__global__ void __launch_bounds__(1024) kBC(
    const float* nin, const float* ein, const float* nqb, const float* eqb,
    const int* src, const int* dst, const int* lgs, const int* lgd)
{
    int tid = threadIdx.x;
    if (blockIdx.x >= 8) {
        int idx = (blockIdx.x - 8) * 1024 + tid;
        if (idx < EE) {
            g_winN[idx] = (g_tab[src[idx] * 3072 + dst[idx]] == idx + 1);
        } else if (idx < EE + ELG) {
            int l = idx - EE;
            g_winL[l] = (g_tab[TABH + lgs[l] * 3072 + lgd[l]] == l + 1);
        }
        return;
    }

    __shared__ __align__(16) float s_rows[128 * 68];  // staging (also phase-1 scratch)
    __shared__ float s_srk[64];
    __shared__ __align__(16) float s_c[4 * 68];
    __shared__ float s_d[4];
    __shared__ float s_red[32];
    __shared__ float s_v;

    int g = blockIdx.x >> 2, h = blockIdx.x & 3;
    const float* in = g ? ein : nin;

    // ---- phase 1: reduce srk partials (48 chunks), scratch = s_rows ----
    float* s_part = s_rows;
    {
        int f = tid & 63, p = tid >> 6;    // 16 groups x 3 chunks
        float a = 0.f;
        #pragma unroll
        for (int q = 0; q < 3; q++)
            a += g_srkp[((g * 48 + p * 3 + q) * 4 + h) * 64 + f];
        s_part[tid] = a;
    }
    __syncthreads();
    if (tid < 64) {
        float a = 0.f;
        #pragma unroll
        for (int p = 0; p < 16; p++) a += s_part[p * 64 + tid];
        s_srk[tid] = a;
    }
    __syncthreads();

    // ---- phase 2: c[j][k] = sum_f Wq[k,64j+f]*srk[f];  d[j] = bq[j]::srk ----
    if (tid < 256) {
        int j = tid & 3, k = tid >> 2;
        const float* wt = g_WT + g * 16384 + j * 4096;   // WT[(j*64+f)*64 + k]
        float a = 0.f;
        #pragma unroll
        for (int f = 0; f < 64; f++)
            a += wt[f * 64 + k] * s_srk[f];
        s_c[j * 68 + k] = a;
    } else if (tid < 260) {
        int j = tid - 256;
        const float* bq = g ? eqb : nqb;
        float dd = 0.f;
        #pragma unroll
        for (int f = 0; f < 64; f++) dd += bq[j * 64 + f] * s_srk[f];
        s_d[j] = dd;
    }
    __syncthreads();

    // ---- phase 3: logits in registers, staged through smem 128 rows/chunk ----
    float x6[6];
    float lmax = -1e30f;
    int ml = tid >> 2, jj = tid & 3;      // (row-in-chunk, j) for tid < 512
    for (int chunk = 0; chunk < 6; chunk++) {
        const float4* src4 =
            (const float4*)(in + (size_t)(h * RPH + chunk * 128) * 64);
        #pragma unroll
        for (int i = 0; i < 2; i++) {
            int idx = i * 1024 + tid;      // 2048 float4 = 128 rows
            int r = idx >> 4, k4 = idx & 15;
            *(float4*)&s_rows[r * 68 + k4 * 4] = src4[idx];
        }
        __syncthreads();
        if (tid < 512) {
            const float4* row = (const float4*)&s_rows[ml * 68];
            const float4* cj  = (const float4*)&s_c[jj * 68];
            float a0 = 0.f, a1 = 0.f, a2 = 0.f, a3 = 0.f;
            #pragma unroll
            for (int k = 0; k < 16; k += 4) {
                float4 r0 = row[k + 0], c0 = cj[k + 0];
                float4 r1 = row[k + 1], c1 = cj[k + 1];
                float4 r2 = row[k + 2], c2 = cj[k + 2];
                float4 r3 = row[k + 3], c3 = cj[k + 3];
                a0 += r0.x * c0.x + r0.y * c0.y + r0.z * c0.z + r0.w * c0.w;
                a1 += r1.x * c1.x + r1.y * c1.y + r1.z * c1.z + r1.w * c1.w;
                a2 += r2.x * c2.x + r2.y * c2.y + r2.z * c2.z + r2.w * c2.w;
                a3 += r3.x * c3.x + r3.y * c3.y + r3.z * c3.z + r3.w * c3.w;
            }
            float x = (s_d[jj] + ((a0 + a1) + (a2 + a3))) * 0.125f;
            x6[chunk] = x;
            lmax = fmaxf(lmax, x);
        }
        __syncthreads();
    }

    // ---- phase 4: softmax over 3072 (values live in x6 of threads < 512) ----
    #pragma unroll
    for (int o = 16; o > 0; o >>= 1)
        lmax = fmaxf(lmax, __shfl_xor_sync(0xffffffffu, lmax, o));
    if ((tid & 31) == 0) s_red[tid >> 5] = lmax;
    __syncthreads();
    if (tid == 0) {
        float m2 = s_red[0];
        #pragma unroll
        for (int i = 1; i < 32; i++) m2 = fmaxf(m2, s_red[i]);
        s_v = m2;
    }
    __syncthreads();
    float mx = s_v;
    float e6[6];
    float lsum = 0.f;
    if (tid < 512) {
        #pragma unroll
        for (int c = 0; c < 6; c++) {
            e6[c] = __expf(x6[c] - mx);
            lsum += e6[c];
        }
    }
    #pragma unroll
    for (int o = 16; o > 0; o >>= 1)
        lsum += __shfl_xor_sync(0xffffffffu, lsum, o);
    __syncthreads();
    if ((tid & 31) == 0) s_red[tid >> 5] = lsum;
    __syncthreads();
    if (tid == 0) {
        float s = 0.f;
        #pragma unroll
        for (int i = 0; i < 32; i++) s += s_red[i];
        s_v = 1.f / s;
    }
    __syncthreads();
    float inv = s_v;
    if (tid < 512) {
        float* att = g_att + (g * 4 + h) * 3072;
        #pragma unroll
        for (int c = 0; c < 6; c++)
            att[(c * 128 + ml) * 4 + jj] = e6[c] * inv;
    }
}

// ======= kernel D: message-passing scatter (16 lanes/edge, float4 atomics) =======
// blocks 0-35 also reset the tournament table (nothing reads g_tab this launch)
__global__ void __launch_bounds__(256) kD(
    const int* src, const int* dst, const int* lgs, const int* lgd, float* out)
{
    int tid = threadIdx.x;
    int bx = blockIdx.x;

    if (bx < 36) {
        int e = bx * 256 + tid;
        if (e < EE) g_tab[src[e] * 3072 + dst[e]] = 0;
        else {
            int l = e - EE;
            g_tab[TABH + lgs[l] * 3072 + lgd[l]] = 0;
        }
    }

    int u = tid >> 4;            // 16 edges per block
    int q = (tid & 15) * 4;      // float4 lane within feature dim
    if (bx < 192) {                                    // node messages (edge att, g=1)
        int e = bx * 16 + u;
        if (!g_winN[e]) return;
        int s = src[e], d = dst[e];
        float4 acc = make_float4(0.f, 0.f, 0.f, 0.f);
        #pragma unroll
        for (int h = 0; h < 4; h++) {
            float a = __ldg(&g_att[(4 + h) * 3072 + e]);
            float4 v = *(const float4*)&g_NV[((size_t)(h * 3072 + d)) * 64 + q];
            acc.x += a * v.x; acc.y += a * v.y; acc.z += a * v.z; acc.w += a * v.w;
        }
        acc.x *= 0.25f; acc.y *= 0.25f; acc.z *= 0.25f; acc.w *= 0.25f;
        atomicAdd((float4*)&out[s * 64 + q], acc);     // mean over heads
    } else {                                           // line-graph messages (node att, g=0)
        int l = (bx - 192) * 16 + u;
        if (!g_winL[l]) return;
        int e1 = lgs[l], e2 = lgd[l];
        int c = dst[e1];
        float4 acc = make_float4(0.f, 0.f, 0.f, 0.f);
        #pragma unroll
        for (int h = 0; h < 4; h++) {
            float a = __ldg(&g_att[h * 3072 + c]);
            float4 v = *(const float4*)&g_EV[((size_t)(h * 3072 + e2)) * 64 + q];
            acc.x += a * v.x; acc.y += a * v.y; acc.z += a * v.z; acc.w += a * v.w;
        }
        acc.x *= 0.25f; acc.y *= 0.25f; acc.z *= 0.25f; acc.w *= 0.25f;
        atomicAdd((float4*)&out[NN * 64 + e1 * 64 + q], acc);
    }
}

extern "C" void kernel_launch(void* const* d_in, const int* in_sizes, int n_in,
                              void* d_out, int out_size)
{
    const float* nin = (const float*)d_in[0];
    const float* ein = (const float*)d_in[1];
    const int* src = (const int*)d_in[2];
    const int* dst = (const int*)d_in[3];
    const int* lgs = (const int*)d_in[4];
    const int* lgd = (const int*)d_in[5];
    const float* nqW = (const float*)d_in[6];  const float* nqb = (const float*)d_in[7];
    const float* nkW = (const float*)d_in[8];  const float* nkb = (const float*)d_in[9];
    const float* nvW = (const float*)d_in[10]; const float* nvb = (const float*)d_in[11];
    const float* eqW = (const float*)d_in[12]; const float* eqb = (const float*)d_in[13];
    const float* ekW = (const float*)d_in[14]; const float* ekb = (const float*)d_in[15];
    const float* evW = (const float*)d_in[16]; const float* evb = (const float*)d_in[17];
    float* out = (float*)d_out;

    cudaMemsetAsync(out, 0, (size_t)out_size * sizeof(float));

    kA<<<524, 256>>>(nin, ein, nkW, nkb, ekW, ekb, nvW, nvb, evW, evb,
                     nqW, eqW, src, dst, lgs, lgd);
    kBC<<<17, 1024>>>(nin, ein, nqb, eqb, src, dst, lgs, lgd);
    kD<<<576, 256>>>(src, dst, lgs, lgd, out);
}

// round 10
// speedup vs baseline: 1.3944x; 1.1593x over previous
#include <cuda_runtime.h>

#define NN   3072
#define EE   3072
#define ELG  6144
#define FF   64
#define HH   4
#define RPH  768        // input rows per head after .view scramble
#define TABH 9437184    // 3072*3072, lg keys offset by this

// -------- scratch (__device__ globals; no allocations allowed) --------
__device__ float g_NV[NN * 256];
__device__ float g_EV[EE * 256];
__device__ float g_srkp[2 * 48 * 4 * 64];   // partial srk sums [g][chunk][h][f]
__device__ float g_WT[2 * 256 * 64];        // transposed Wq (node, edge)
__device__ float g_att[2 * 4 * 3072];       // g=0: node att, g=1: edge att
__device__ float g_logit[8 * 3072];         // raw logits per (g,h)
__device__ float g_pmax[48];                // per-(gh,chunk) partial max
__device__ int   g_cnt[8];                  // arrival counters (zero invariant)
__device__ unsigned char g_winN[EE];
__device__ unsigned char g_winL[ELG];
__device__ int g_tab[2 * TABH];             // dedup tournament table (zero invariant)

// packed f32x2 helpers (FFMA2 path — ptxas never emits this from plain C++)
__device__ __forceinline__ unsigned long long pk2(float w) {
    unsigned long long r;
    asm("mov.b64 %0, {%1, %1};" : "=l"(r) : "f"(w));
    return r;
}
__device__ __forceinline__ void ffma2(unsigned long long& d,
                                      unsigned long long a, unsigned long long b) {
    asm("fma.rn.f32x2 %0, %1, %2, %0;" : "+l"(d) : "l"(a), "l"(b));
}
__device__ __forceinline__ void unpk2(unsigned long long v, float& lo, float& hi) {
    asm("mov.b64 {%0, %1}, %2;" : "=f"(lo), "=f"(hi) : "l"(v));
}

// ======================= kernel A: all input-only work =======================
// roles by blockIdx.x:
//   [0,96)      srk partials (fused K projection, never materialized)
//   [96,480)    V gemms: 64x64 tiles, NV (192 blocks), EV (192 blocks)
//   [480,516)   dedup atomicMax tournament (9216 edges)
//   [516,524)   transpose Wq (node 4 tiles, edge 4 tiles)
__global__ void __launch_bounds__(256) kA(
    const float* nin, const float* ein,
    const float* nkW, const float* nkb, const float* ekW, const float* ekb,
    const float* nvW, const float* nvb, const float* evW, const float* evb,
    const float* nqW, const float* eqW,
    const int* src, const int* dst, const int* lgs, const int* lgd)
{
    __shared__ __align__(16) float sm[8512];   // unioned per role (~34KB)
    int b = blockIdx.x, tid = threadIdx.x;

    if (b < 96) {
        // ---- srk role: chunk of 64 nodes (16 KM rows per head) ----
        int g = b / 48, chunk = b % 48;
        const float* in = g ? ein : nin;
        const float* W  = g ? ekW : nkW;
        const float* bk = g ? ekb : nkb;
        float* s_in4 = sm;           // 4 heads * 16 rows * stride 68 = 4352
        float* s_wT  = sm + 4352;    // 4 * 68
        float* s_km  = sm + 4624;    // 4 * 64

        {   // vectorized fill: 256 float4 per head-slice = 1/thread
            const float4* in4g = (const float4*)in;
            int rr = tid >> 4, k4 = tid & 15;
            #pragma unroll
            for (int h2 = 0; h2 < 4; h2++)
                *(float4*)&s_in4[h2 * 1088 + rr * 68 + k4 * 4] =
                    in4g[(h2 * RPH + chunk * 16 + rr) * 16 + k4];
        }
        {   // transpose tiny K weights: s_wT[c][k] = W[k*4+c]
            int k = tid >> 2, c = tid & 3;
            s_wT[c * 68 + k] = W[tid];
        }
        __syncthreads();
        // phase 1: k[h, n] = KM[h*768 + n/4, n%4]
        int h = tid >> 6, idx = tid & 63;
        int rl = idx >> 2, c = idx & 3;
        float acc = bk[c];
        const float4* arow = (const float4*)&s_in4[h * 1088 + rl * 68];
        const float4* wrow = (const float4*)&s_wT[c * 68];
        #pragma unroll
        for (int k4 = 0; k4 < 16; k4++) {
            float4 a = arow[k4], w = wrow[k4];
            acc += a.x * w.x + a.y * w.y + a.z * w.z + a.w * w.w;
        }
        s_km[h * 64 + rl * 4 + c] = acc;   // index == h*64 + local n
        __syncthreads();
        // phase 2: srk partial: srk[h,f] += in[n,f] * k[h,n] over 64 n
        int f = tid & 63;
        float sacc = 0.f;
        int n0 = chunk * 64;
        #pragma unroll 8
        for (int nl = 0; nl < 64; nl++)
            sacc += in[(n0 + nl) * 64 + f] * s_km[h * 64 + nl];
        g_srkp[((g * 48 + chunk) * 4 + h) * 64 + f] = sacc;

    } else if (b < 480) {
        // ---- V gemm role: [3072x64] @ [64x256] + bias, f32x2-packed ----
        int i2 = b - 96;
        int mat = i2 / 192;
        int rem = i2 % 192;
        int r0 = (rem >> 2) * 64, c0 = (rem & 3) * 64;
        const float* in = mat ? ein : nin;
        const float* W  = mat ? evW : nvW;
        const float* bb = mat ? evb : nvb;
        float* outv     = mat ? g_EV : g_NV;
        float* As = sm;                  // 64 k * stride 68 = 4352
        float* Ws = sm + 4352;           // 64*64
        float* Bs = sm + 8448;           // 64

        #pragma unroll
        for (int i = 0; i < 16; i++) {   // A tile, transposed store (k-major)
            int idx = i * 256 + tid;
            int r = idx >> 6, k = idx & 63;
            As[k * 68 + r] = in[r0 * 64 + idx];
        }
        #pragma unroll
        for (int i = 0; i < 4; i++) {    // W tile, vectorized copy
            int idx = i * 256 + tid;
            int k = idx >> 4, c4 = idx & 15;
            *(float4*)&Ws[k * 64 + c4 * 4] =
                *(const float4*)&W[k * 256 + c0 + c4 * 4];
        }
        if (tid < 64) Bs[tid] = bb[c0 + tid];
        __syncthreads();

        int tx = tid & 15, ty = tid >> 4;
        int rl = ty * 4, cl = tx * 4;
        unsigned long long acc2[2][4];   // row-pairs (rl+2p, rl+2p+1) x 4 cols
        #pragma unroll
        for (int j = 0; j < 4; j++) {
            unsigned long long p = pk2(Bs[cl + j]);
            acc2[0][j] = p; acc2[1][j] = p;
        }

        #pragma unroll 16
        for (int k = 0; k < 64; k++) {
            ulonglong2 a = *(const ulonglong2*)&As[k * 68 + rl];
            float4 w = *(const float4*)&Ws[k * 64 + cl];
            unsigned long long wx = pk2(w.x), wy = pk2(w.y),
                               wz = pk2(w.z), ww = pk2(w.w);
            ffma2(acc2[0][0], a.x, wx); ffma2(acc2[1][0], a.y, wx);
            ffma2(acc2[0][1], a.x, wy); ffma2(acc2[1][1], a.y, wy);
            ffma2(acc2[0][2], a.x, wz); ffma2(acc2[1][2], a.y, wz);
            ffma2(acc2[0][3], a.x, ww); ffma2(acc2[1][3], a.y, ww);
        }
        #pragma unroll
        for (int p = 0; p < 2; p++) {
            float lo[4], hi[4];
            #pragma unroll
            for (int j = 0; j < 4; j++) unpk2(acc2[p][j], lo[j], hi[j]);
            *(float4*)&outv[(r0 + rl + 2 * p)     * 256 + c0 + cl] =
                make_float4(lo[0], lo[1], lo[2], lo[3]);
            *(float4*)&outv[(r0 + rl + 2 * p + 1) * 256 + c0 + cl] =
                make_float4(hi[0], hi[1], hi[2], hi[3]);
        }

    } else if (b < 516) {
        // ---- dedup tournament: atomicMax(tab[key], e+1) ----
        int e = (b - 480) * 256 + tid;
        if (e < EE) {
            atomicMax(&g_tab[src[e] * 3072 + dst[e]], e + 1);
        } else {
            int l = e - EE;
            atomicMax(&g_tab[TABH + lgs[l] * 3072 + lgd[l]], l + 1);
        }

    } else {
        // ---- transpose Wq: [64k][256c] -> WT[256c][64k] ----
        int t = b - 516;
        int mat = t >> 2, tile = t & 3;
        const float* W = mat ? eqW : nqW;
        float* s = sm;   // 64*65
        #pragma unroll
        for (int i = 0; i < 16; i++) {
            int idx = i * 256 + tid;
            int k = idx >> 6, c = idx & 63;
            s[k * 65 + c] = W[k * 256 + tile * 64 + c];
        }
        __syncthreads();
        #pragma unroll
        for (int i = 0; i < 16; i++) {
            int idx = i * 256 + tid;
            int c = idx >> 6, k = idx & 63;
            g_WT[mat * 16384 + (tile * 64 + c) * 64 + k] = s[k * 65 + c];
        }
    }
}

// ===== kernel BC: parallel logits + last-block softmax =====
// blocks [0,48): worker (gh = b/6, chunk = b%6): srk-reduce + c/d + 128-row
//   logit chunk -> gmem; last arriver per gh does the softmax.
// blocks [48,57): read dedup winners from tournament table.
__global__ void __launch_bounds__(1024) kBC(
    const float* nin, const float* ein, const float* nqb, const float* eqb,
    const int* src, const int* dst, const int* lgs, const int* lgd)
{
    int tid = threadIdx.x;
    if (blockIdx.x >= 48) {
        int idx = (blockIdx.x - 48) * 1024 + tid;
        if (idx < EE) {
            g_winN[idx] = (g_tab[src[idx] * 3072 + dst[idx]] == idx + 1);
        } else if (idx < EE + ELG) {
            int l = idx - EE;
            g_winL[l] = (g_tab[TABH + lgs[l] * 3072 + lgd[l]] == l + 1);
        }
        return;
    }

    __shared__ __align__(16) float s_rows[128 * 68];  // staging / phase-1 scratch
    __shared__ float s_srk[64];
    __shared__ __align__(16) float s_c[4 * 68];
    __shared__ float s_d[4];
    __shared__ float s_red[32];
    __shared__ float s_v;
    __shared__ int s_last;

    int b = blockIdx.x;
    int gh = b / 6, chunk = b % 6;
    int g = gh >> 2, h = gh & 3;
    const float* in = g ? ein : nin;

    // ---- phase 1: reduce srk partials (48 chunks), scratch = s_rows ----
    float* s_part = s_rows;
    {
        int f = tid & 63, p = tid >> 6;    // 16 groups x 3 chunks
        float a = 0.f;
        #pragma unroll
        for (int q = 0; q < 3; q++)
            a += g_srkp[((g * 48 + p * 3 + q) * 4 + h) * 64 + f];
        s_part[tid] = a;
    }
    __syncthreads();
    if (tid < 64) {
        float a = 0.f;
        #pragma unroll
        for (int p = 0; p < 16; p++) a += s_part[p * 64 + tid];
        s_srk[tid] = a;
    }
    __syncthreads();

    // ---- phase 2: c[j][k] = sum_f Wq[k,64j+f]*srk[f];  d[j] = bq[j]::srk ----
    if (tid < 256) {
        int j = tid & 3, k = tid >> 2;
        const float* wt = g_WT + g * 16384 + j * 4096;   // WT[(j*64+f)*64 + k]
        float a = 0.f;
        #pragma unroll
        for (int f = 0; f < 64; f++)
            a += wt[f * 64 + k] * s_srk[f];
        s_c[j * 68 + k] = a;
    } else if (tid < 260) {
        int j = tid - 256;
        const float* bq = g ? eqb : nqb;
        float dd = 0.f;
        #pragma unroll
        for (int f = 0; f < 64; f++) dd += bq[j * 64 + f] * s_srk[f];
        s_d[j] = dd;
    }
    __syncthreads();

    // ---- phase 3: logits for THIS 128-row chunk only ----
    {
        const float4* src4 =
            (const float4*)(in + (size_t)(h * RPH + chunk * 128) * 64);
        #pragma unroll
        for (int i = 0; i < 2; i++) {
            int idx = i * 1024 + tid;      // 2048 float4 = 128 rows
            int r = idx >> 4, k4 = idx & 15;
            *(float4*)&s_rows[r * 68 + k4 * 4] = src4[idx];
        }
    }
    __syncthreads();
    float lmax = -1e30f;
    if (tid < 512) {
        int ml = tid >> 2, jj = tid & 3;
        const float4* row = (const float4*)&s_rows[ml * 68];
        const float4* cj  = (const float4*)&s_c[jj * 68];
        float a0 = 0.f, a1 = 0.f, a2 = 0.f, a3 = 0.f;
        #pragma unroll
        for (int k = 0; k < 16; k += 4) {
            float4 r0 = row[k + 0], c0 = cj[k + 0];
            float4 r1 = row[k + 1], c1 = cj[k + 1];
            float4 r2 = row[k + 2], c2 = cj[k + 2];
            float4 r3 = row[k + 3], c3 = cj[k + 3];
            a0 += r0.x * c0.x + r0.y * c0.y + r0.z * c0.z + r0.w * c0.w;
            a1 += r1.x * c1.x + r1.y * c1.y + r1.z * c1.z + r1.w * c1.w;
            a2 += r2.x * c2.x + r2.y * c2.y + r2.z * c2.z + r2.w * c2.w;
            a3 += r3.x * c3.x + r3.y * c3.y + r3.z * c3.z + r3.w * c3.w;
        }
        float x = (s_d[tid & 3] + ((a0 + a1) + (a2 + a3))) * 0.125f;
        g_logit[gh * 3072 + chunk * 512 + tid] = x;   // n == chunk*512 + tid
        lmax = x;
    }
    // block max over the 512 logits
    #pragma unroll
    for (int o = 16; o > 0; o >>= 1)
        lmax = fmaxf(lmax, __shfl_xor_sync(0xffffffffu, lmax, o));
    if ((tid & 31) == 0) s_red[tid >> 5] = lmax;
    __syncthreads();
    if (tid == 0) {
        float m2 = s_red[0];
        #pragma unroll
        for (int i = 1; i < 16; i++) m2 = fmaxf(m2, s_red[i]);
        g_pmax[b] = m2;
    }

    // ---- publish & elect last block for this gh ----
    __threadfence();
    __syncthreads();
    if (tid == 0) {
        int old = atomicAdd(&g_cnt[gh], 1);
        s_last = (old == 5);
    }
    __syncthreads();
    if (!s_last) return;
    __threadfence();   // acquire: make peers' logits/pmax visible

    // ---- softmax over all 3072 logits of this gh ----
    float mx = -1e30f;
    #pragma unroll
    for (int c = 0; c < 6; c++) mx = fmaxf(mx, g_pmax[gh * 6 + c]);

    const float* lg = g_logit + gh * 3072;
    float x0 = lg[tid], x1 = lg[tid + 1024], x2 = lg[tid + 2048];
    float e0 = __expf(x0 - mx), e1 = __expf(x1 - mx), e2 = __expf(x2 - mx);
    float lsum = e0 + e1 + e2;
    #pragma unroll
    for (int o = 16; o > 0; o >>= 1)
        lsum += __shfl_xor_sync(0xffffffffu, lsum, o);
    if ((tid & 31) == 0) s_red[tid >> 5] = lsum;
    __syncthreads();
    if (tid == 0) {
        float s = 0.f;
        #pragma unroll
        for (int i = 0; i < 32; i++) s += s_red[i];
        s_v = 1.f / s;
        g_cnt[gh] = 0;                 // restore counter invariant
    }
    __syncthreads();
    float inv = s_v;
    float* att = g_att + gh * 3072;
    att[tid]        = e0 * inv;
    att[tid + 1024] = e1 * inv;
    att[tid + 2048] = e2 * inv;
}

// ======= kernel D: message-passing scatter (16 lanes/edge, float4 atomics) =======
// blocks 0-35 also reset the tournament table (nothing reads g_tab this launch)
__global__ void __launch_bounds__(256) kD(
    const int* src, const int* dst, const int* lgs, const int* lgd, float* out)
{
    int tid = threadIdx.x;
    int bx = blockIdx.x;

    if (bx < 36) {
        int e = bx * 256 + tid;
        if (e < EE) g_tab[src[e] * 3072 + dst[e]] = 0;
        else {
            int l = e - EE;
            g_tab[TABH + lgs[l] * 3072 + lgd[l]] = 0;
        }
    }

    int u = tid >> 4;            // 16 edges per block
    int q = (tid & 15) * 4;      // float4 lane within feature dim
    if (bx < 192) {                                    // node messages (edge att, g=1)
        int e = bx * 16 + u;
        if (!g_winN[e]) return;
        int s = src[e], d = dst[e];
        float4 acc = make_float4(0.f, 0.f, 0.f, 0.f);
        #pragma unroll
        for (int h = 0; h < 4; h++) {
            float a = __ldg(&g_att[(4 + h) * 3072 + e]);
            float4 v = *(const float4*)&g_NV[((size_t)(h * 3072 + d)) * 64 + q];
            acc.x += a * v.x; acc.y += a * v.y; acc.z += a * v.z; acc.w += a * v.w;
        }
        acc.x *= 0.25f; acc.y *= 0.25f; acc.z *= 0.25f; acc.w *= 0.25f;
        atomicAdd((float4*)&out[s * 64 + q], acc);     // mean over heads
    } else {                                           // line-graph messages (node att, g=0)
        int l = (bx - 192) * 16 + u;
        if (!g_winL[l]) return;
        int e1 = lgs[l], e2 = lgd[l];
        int c = dst[e1];
        float4 acc = make_float4(0.f, 0.f, 0.f, 0.f);
        #pragma unroll
        for (int h = 0; h < 4; h++) {
            float a = __ldg(&g_att[h * 3072 + c]);
            float4 v = *(const float4*)&g_EV[((size_t)(h * 3072 + e2)) * 64 + q];
            acc.x += a * v.x; acc.y += a * v.y; acc.z += a * v.z; acc.w += a * v.w;
        }
        acc.x *= 0.25f; acc.y *= 0.25f; acc.z *= 0.25f; acc.w *= 0.25f;
        atomicAdd((float4*)&out[NN * 64 + e1 * 64 + q], acc);
    }
}

extern "C" void kernel_launch(void* const* d_in, const int* in_sizes, int n_in,
                              void* d_out, int out_size)
{
    const float* nin = (const float*)d_in[0];
    const float* ein = (const float*)d_in[1];
    const int* src = (const int*)d_in[2];
    const int* dst = (const int*)d_in[3];
    const int* lgs = (const int*)d_in[4];
    const int* lgd = (const int*)d_in[5];
    const float* nqW = (const float*)d_in[6];  const float* nqb = (const float*)d_in[7];
    const float* nkW = (const float*)d_in[8];  const float* nkb = (const float*)d_in[9];
    const float* nvW = (const float*)d_in[10]; const float* nvb = (const float*)d_in[11];
    const float* eqW = (const float*)d_in[12]; const float* eqb = (const float*)d_in[13];
    const float* ekW = (const float*)d_in[14]; const float* ekb = (const float*)d_in[15];
    const float* evW = (const float*)d_in[16]; const float* evb = (const float*)d_in[17];
    float* out = (float*)d_out;

    cudaMemsetAsync(out, 0, (size_t)out_size * sizeof(float));

    kA<<<524, 256>>>(nin, ein, nkW, nkb, ekW, ekb, nvW, nvb, evW, evb,
                     nqW, eqW, src, dst, lgs, lgd);
    kBC<<<57, 1024>>>(nin, ein, nqb, eqb, src, dst, lgs, lgd);
    kD<<<576, 256>>>(src, dst, lgs, lgd, out);
}

// round 11
// speedup vs baseline: 1.4069x; 1.0089x over previous
#include <cuda_runtime.h>

#define NN   3072
#define EE   3072
#define ELG  6144
#define FF   64
#define HH   4
#define RPH  768        // input rows per head after .view scramble
#define TABH 9437184    // 3072*3072, lg keys offset by this

// -------- scratch (__device__ globals; no allocations allowed) --------
__device__ float g_NV[NN * 256];
__device__ float g_EV[EE * 256];
__device__ float g_srkp[2 * 48 * 4 * 64];   // partial srk sums [g][chunk][h][f]
__device__ float g_WT[2 * 256 * 64];        // transposed Wq (node, edge)
__device__ float g_att[2 * 4 * 3072];       // g=0: node att, g=1: edge att
__device__ float g_logit[8 * 3072];         // raw logits per (g,h)
__device__ float g_pmax[48];                // per-(gh,chunk) partial max
__device__ int   g_cnt[8];                  // softmax arrival counters (zero invariant)
__device__ int   c_srk, c_wt, c_tab;        // role-completion counters (zero invariant)
__device__ unsigned char g_winN[EE];
__device__ unsigned char g_winL[ELG];
__device__ int g_tab[2 * TABH];             // dedup tournament table (zero invariant)

// packed f32x2 helpers (FFMA2 path — ptxas never emits this from plain C++)
__device__ __forceinline__ unsigned long long pk2(float w) {
    unsigned long long r;
    asm("mov.b64 %0, {%1, %1};" : "=l"(r) : "f"(w));
    return r;
}
__device__ __forceinline__ void ffma2(unsigned long long& d,
                                      unsigned long long a, unsigned long long b) {
    asm("fma.rn.f32x2 %0, %1, %2, %0;" : "+l"(d) : "l"(a), "l"(b));
}
__device__ __forceinline__ void unpk2(unsigned long long v, float& lo, float& hi) {
    asm("mov.b64 {%0, %1}, %2;" : "=f"(lo), "=f"(hi) : "l"(v));
}

__device__ __forceinline__ void spin_until(volatile int* ctr, int target) {
    // called by thread 0 only; acquire fence after
    while (*ctr != target) {}
    __threadfence();
}

// ============ kernel A: everything except the final scatter ============
// roles by blockIdx.x (producers get lowest bids -> wave 1):
//   [0,96)      srk partials (fused K projection)        -> c_srk
//   [96,104)    transpose Wq                             -> c_wt
//   [104,140)   dedup atomicMax tournament               -> c_tab
//   [140,524)   V gemms: 64x64 tiles (NV 192, EV 192)
//   [524,572)   kBC workers (spin on c_srk,c_wt): logits + last-block softmax
//   [572,608)   winner readers (spin on c_tab)
__global__ void __launch_bounds__(256, 4) kA(
    const float* nin, const float* ein,
    const float* nkW, const float* nkb, const float* ekW, const float* ekb,
    const float* nvW, const float* nvb, const float* evW, const float* evb,
    const float* nqW, const float* eqW, const float* nqb, const float* eqb,
    const int* src, const int* dst, const int* lgs, const int* lgd)
{
    __shared__ __align__(16) float sm[8704];   // big staging union (34.8KB)
    __shared__ float s_srk[64];
    __shared__ __align__(16) float s_c[4 * 68];
    __shared__ float s_d[4];
    __shared__ float s_red[8];
    __shared__ float s_v;
    __shared__ int s_last;
    int b = blockIdx.x, tid = threadIdx.x;

    if (b < 96) {
        // ---- srk role: chunk of 64 nodes (16 KM rows per head) ----
        int g = b / 48, chunk = b % 48;
        const float* in = g ? ein : nin;
        const float* W  = g ? ekW : nkW;
        const float* bk = g ? ekb : nkb;
        float* s_in4 = sm;           // 4 heads * 16 rows * stride 68 = 4352
        float* s_wT  = sm + 4352;    // 4 * 68
        float* s_km  = sm + 4624;    // 4 * 64

        {   // vectorized fill
            const float4* in4g = (const float4*)in;
            int rr = tid >> 4, k4 = tid & 15;
            #pragma unroll
            for (int h2 = 0; h2 < 4; h2++)
                *(float4*)&s_in4[h2 * 1088 + rr * 68 + k4 * 4] =
                    in4g[(h2 * RPH + chunk * 16 + rr) * 16 + k4];
        }
        {   // transpose tiny K weights
            int k = tid >> 2, c = tid & 3;
            s_wT[c * 68 + k] = W[tid];
        }
        __syncthreads();
        int h = tid >> 6, idx = tid & 63;
        int rl = idx >> 2, c = idx & 3;
        float acc = bk[c];
        const float4* arow = (const float4*)&s_in4[h * 1088 + rl * 68];
        const float4* wrow = (const float4*)&s_wT[c * 68];
        #pragma unroll
        for (int k4 = 0; k4 < 16; k4++) {
            float4 a = arow[k4], w = wrow[k4];
            acc += a.x * w.x + a.y * w.y + a.z * w.z + a.w * w.w;
        }
        s_km[h * 64 + rl * 4 + c] = acc;
        __syncthreads();
        int f = tid & 63;
        float sacc = 0.f;
        int n0 = chunk * 64;
        #pragma unroll 8
        for (int nl = 0; nl < 64; nl++)
            sacc += in[(n0 + nl) * 64 + f] * s_km[h * 64 + nl];
        g_srkp[((g * 48 + chunk) * 4 + h) * 64 + f] = sacc;
        __threadfence();
        __syncthreads();
        if (tid == 0) atomicAdd(&c_srk, 1);

    } else if (b < 104) {
        // ---- transpose Wq: [64k][256c] -> WT[256c][64k] ----
        int t = b - 96;
        int mat = t >> 2, tile = t & 3;
        const float* W = mat ? eqW : nqW;
        float* s = sm;
        #pragma unroll
        for (int i = 0; i < 16; i++) {
            int idx = i * 256 + tid;
            int k = idx >> 6, c = idx & 63;
            s[k * 65 + c] = W[k * 256 + tile * 64 + c];
        }
        __syncthreads();
        #pragma unroll
        for (int i = 0; i < 16; i++) {
            int idx = i * 256 + tid;
            int c = idx >> 6, k = idx & 63;
            g_WT[mat * 16384 + (tile * 64 + c) * 64 + k] = s[k * 65 + c];
        }
        __threadfence();
        __syncthreads();
        if (tid == 0) atomicAdd(&c_wt, 1);

    } else if (b < 140) {
        // ---- dedup tournament: atomicMax(tab[key], e+1) ----
        int e = (b - 104) * 256 + tid;
        if (e < EE) {
            atomicMax(&g_tab[src[e] * 3072 + dst[e]], e + 1);
        } else {
            int l = e - EE;
            atomicMax(&g_tab[TABH + lgs[l] * 3072 + lgd[l]], l + 1);
        }
        __threadfence();
        __syncthreads();
        if (tid == 0) atomicAdd(&c_tab, 1);

    } else if (b < 524) {
        // ---- V gemm role: [3072x64] @ [64x256] + bias, f32x2-packed ----
        int i2 = b - 140;
        int mat = i2 / 192;
        int rem = i2 % 192;
        int r0 = (rem >> 2) * 64, c0 = (rem & 3) * 64;
        const float* in = mat ? ein : nin;
        const float* W  = mat ? evW : nvW;
        const float* bb = mat ? evb : nvb;
        float* outv     = mat ? g_EV : g_NV;
        float* As = sm;                  // 64 k * stride 68 = 4352
        float* Ws = sm + 4352;           // 64*64
        float* Bs = sm + 8448;           // 64

        #pragma unroll
        for (int i = 0; i < 16; i++) {   // A tile, transposed store (k-major)
            int idx = i * 256 + tid;
            int r = idx >> 6, k = idx & 63;
            As[k * 68 + r] = in[r0 * 64 + idx];
        }
        #pragma unroll
        for (int i = 0; i < 4; i++) {    // W tile, vectorized copy
            int idx = i * 256 + tid;
            int k = idx >> 4, c4 = idx & 15;
            *(float4*)&Ws[k * 64 + c4 * 4] =
                *(const float4*)&W[k * 256 + c0 + c4 * 4];
        }
        if (tid < 64) Bs[tid] = bb[c0 + tid];
        __syncthreads();

        int tx = tid & 15, ty = tid >> 4;
        int rl = ty * 4, cl = tx * 4;
        unsigned long long acc2[2][4];
        #pragma unroll
        for (int j = 0; j < 4; j++) {
            unsigned long long p = pk2(Bs[cl + j]);
            acc2[0][j] = p; acc2[1][j] = p;
        }

        #pragma unroll 16
        for (int k = 0; k < 64; k++) {
            ulonglong2 a = *(const ulonglong2*)&As[k * 68 + rl];
            float4 w = *(const float4*)&Ws[k * 64 + cl];
            unsigned long long wx = pk2(w.x), wy = pk2(w.y),
                               wz = pk2(w.z), ww = pk2(w.w);
            ffma2(acc2[0][0], a.x, wx); ffma2(acc2[1][0], a.y, wx);
            ffma2(acc2[0][1], a.x, wy); ffma2(acc2[1][1], a.y, wy);
            ffma2(acc2[0][2], a.x, wz); ffma2(acc2[1][2], a.y, wz);
            ffma2(acc2[0][3], a.x, ww); ffma2(acc2[1][3], a.y, ww);
        }
        #pragma unroll
        for (int p = 0; p < 2; p++) {
            float lo[4], hi[4];
            #pragma unroll
            for (int j = 0; j < 4; j++) unpk2(acc2[p][j], lo[j], hi[j]);
            *(float4*)&outv[(r0 + rl + 2 * p)     * 256 + c0 + cl] =
                make_float4(lo[0], lo[1], lo[2], lo[3]);
            *(float4*)&outv[(r0 + rl + 2 * p + 1) * 256 + c0 + cl] =
                make_float4(hi[0], hi[1], hi[2], hi[3]);
        }

    } else if (b < 572) {
        // ---- kBC worker: (gh, chunk) logits + last-block softmax ----
        int w = b - 524;
        int gh = w / 6, chunk = w % 6;
        int g = gh >> 2, h = gh & 3;
        const float* in = g ? ein : nin;

        if (tid == 0) {
            spin_until(&c_srk, 96);
            spin_until(&c_wt, 8);
        }
        __syncthreads();

        // phase 1: reduce srk partials (48 chunks), scratch = sm
        {
            int f = tid & 63, p = tid >> 6;    // 4 groups x 12 chunks
            float a = 0.f;
            #pragma unroll
            for (int q = 0; q < 12; q++)
                a += g_srkp[((g * 48 + p * 12 + q) * 4 + h) * 64 + f];
            sm[tid] = a;
        }
        __syncthreads();
        if (tid < 64)
            s_srk[tid] = sm[tid] + sm[64 + tid] + sm[128 + tid] + sm[192 + tid];
        __syncthreads();

        // phase 2: c[j][k], d[j]
        {
            int j = tid & 3, k = tid >> 2;
            const float* wt = g_WT + g * 16384 + j * 4096;
            float a = 0.f;
            #pragma unroll 16
            for (int f = 0; f < 64; f++)
                a += wt[f * 64 + k] * s_srk[f];
            s_c[j * 68 + k] = a;
        }
        if (tid < 4) {
            const float* bq = g ? eqb : nqb;
            float dd = 0.f;
            #pragma unroll 16
            for (int f = 0; f < 64; f++) dd += bq[tid * 64 + f] * s_srk[f];
            s_d[tid] = dd;
        }
        __syncthreads();

        // phase 3: logits for this 128-row chunk (512 positions, 2/thread)
        {
            const float4* src4 =
                (const float4*)(in + (size_t)(h * RPH + chunk * 128) * 64);
            #pragma unroll
            for (int i = 0; i < 8; i++) {
                int idx = i * 256 + tid;
                int r = idx >> 4, k4 = idx & 15;
                *(float4*)&sm[r * 68 + k4 * 4] = src4[idx];
            }
        }
        __syncthreads();
        float lmax = -1e30f;
        #pragma unroll
        for (int it = 0; it < 2; it++) {
            int pos = it * 256 + tid;
            int ml = pos >> 2, jj = pos & 3;
            const float4* row = (const float4*)&sm[ml * 68];
            const float4* cj  = (const float4*)&s_c[jj * 68];
            float a0 = 0.f, a1 = 0.f, a2 = 0.f, a3 = 0.f;
            #pragma unroll
            for (int k = 0; k < 16; k += 4) {
                float4 r0 = row[k + 0], c0 = cj[k + 0];
                float4 r1 = row[k + 1], c1 = cj[k + 1];
                float4 r2 = row[k + 2], c2 = cj[k + 2];
                float4 r3 = row[k + 3], c3 = cj[k + 3];
                a0 += r0.x * c0.x + r0.y * c0.y + r0.z * c0.z + r0.w * c0.w;
                a1 += r1.x * c1.x + r1.y * c1.y + r1.z * c1.z + r1.w * c1.w;
                a2 += r2.x * c2.x + r2.y * c2.y + r2.z * c2.z + r2.w * c2.w;
                a3 += r3.x * c3.x + r3.y * c3.y + r3.z * c3.z + r3.w * c3.w;
            }
            float x = (s_d[jj] + ((a0 + a1) + (a2 + a3))) * 0.125f;
            g_logit[gh * 3072 + chunk * 512 + pos] = x;
            lmax = fmaxf(lmax, x);
        }
        #pragma unroll
        for (int o = 16; o > 0; o >>= 1)
            lmax = fmaxf(lmax, __shfl_xor_sync(0xffffffffu, lmax, o));
        if ((tid & 31) == 0) s_red[tid >> 5] = lmax;
        __syncthreads();
        if (tid == 0) {
            float m2 = s_red[0];
            #pragma unroll
            for (int i = 1; i < 8; i++) m2 = fmaxf(m2, s_red[i]);
            g_pmax[w] = m2;
        }
        __threadfence();
        __syncthreads();
        if (tid == 0) {
            int old = atomicAdd(&g_cnt[gh], 1);
            s_last = (old == 5);
        }
        __syncthreads();
        if (!s_last) return;
        __threadfence();

        // last arriver: softmax over all 3072 logits of this gh
        float mx = -1e30f;
        #pragma unroll
        for (int c = 0; c < 6; c++) mx = fmaxf(mx, g_pmax[gh * 6 + c]);
        const float* lg = g_logit + gh * 3072;
        float* att = g_att + gh * 3072;
        float lsum = 0.f;
        #pragma unroll
        for (int i = 0; i < 12; i++) {
            float e = __expf(lg[i * 256 + tid] - mx);
            att[i * 256 + tid] = e;
            lsum += e;
        }
        #pragma unroll
        for (int o = 16; o > 0; o >>= 1)
            lsum += __shfl_xor_sync(0xffffffffu, lsum, o);
        if ((tid & 31) == 0) s_red[tid >> 5] = lsum;
        __syncthreads();
        if (tid == 0) {
            float s = 0.f;
            #pragma unroll
            for (int i = 0; i < 8; i++) s += s_red[i];
            s_v = 1.f / s;
            g_cnt[gh] = 0;             // restore counter invariant
        }
        __syncthreads();
        float inv = s_v;
        #pragma unroll
        for (int i = 0; i < 12; i++)
            att[i * 256 + tid] *= inv;

    } else {
        // ---- winner readers: spin on tab completion ----
        if (tid == 0) spin_until(&c_tab, 36);
        __syncthreads();
        int idx = (b - 572) * 256 + tid;
        if (idx < EE) {
            g_winN[idx] = (g_tab[src[idx] * 3072 + dst[idx]] == idx + 1);
        } else {
            int l = idx - EE;
            g_winL[l] = (g_tab[TABH + lgs[l] * 3072 + lgd[l]] == l + 1);
        }
    }
}

// ======= kernel D: message-passing scatter (16 lanes/edge, float4 atomics) =======
// blocks 0-35 also reset the tournament table; block 36 resets role counters
__global__ void __launch_bounds__(256) kD(
    const int* src, const int* dst, const int* lgs, const int* lgd, float* out)
{
    int tid = threadIdx.x;
    int bx = blockIdx.x;

    if (bx < 36) {
        int e = bx * 256 + tid;
        if (e < EE) g_tab[src[e] * 3072 + dst[e]] = 0;
        else {
            int l = e - EE;
            g_tab[TABH + lgs[l] * 3072 + lgd[l]] = 0;
        }
    } else if (bx == 36 && tid < 3) {
        if (tid == 0) c_srk = 0;
        else if (tid == 1) c_wt = 0;
        else c_tab = 0;
    }

    int u = tid >> 4;            // 16 edges per block
    int q = (tid & 15) * 4;      // float4 lane within feature dim
    if (bx < 192) {                                    // node messages (edge att, g=1)
        int e = bx * 16 + u;
        if (!g_winN[e]) return;
        int s = src[e], d = dst[e];
        float4 acc = make_float4(0.f, 0.f, 0.f, 0.f);
        #pragma unroll
        for (int h = 0; h < 4; h++) {
            float a = __ldg(&g_att[(4 + h) * 3072 + e]);
            float4 v = *(const float4*)&g_NV[((size_t)(h * 3072 + d)) * 64 + q];
            acc.x += a * v.x; acc.y += a * v.y; acc.z += a * v.z; acc.w += a * v.w;
        }
        acc.x *= 0.25f; acc.y *= 0.25f; acc.z *= 0.25f; acc.w *= 0.25f;
        atomicAdd((float4*)&out[s * 64 + q], acc);     // mean over heads
    } else {                                           // line-graph messages (node att, g=0)
        int l = (bx - 192) * 16 + u;
        if (!g_winL[l]) return;
        int e1 = lgs[l], e2 = lgd[l];
        int c = dst[e1];
        float4 acc = make_float4(0.f, 0.f, 0.f, 0.f);
        #pragma unroll
        for (int h = 0; h < 4; h++) {
            float a = __ldg(&g_att[h * 3072 + c]);
            float4 v = *(const float4*)&g_EV[((size_t)(h * 3072 + e2)) * 64 + q];
            acc.x += a * v.x; acc.y += a * v.y; acc.z += a * v.z; acc.w += a * v.w;
        }
        acc.x *= 0.25f; acc.y *= 0.25f; acc.z *= 0.25f; acc.w *= 0.25f;
        atomicAdd((float4*)&out[NN * 64 + e1 * 64 + q], acc);
    }
}

extern "C" void kernel_launch(void* const* d_in, const int* in_sizes, int n_in,
                              void* d_out, int out_size)
{
    const float* nin = (const float*)d_in[0];
    const float* ein = (const float*)d_in[1];
    const int* src = (const int*)d_in[2];
    const int* dst = (const int*)d_in[3];
    const int* lgs = (const int*)d_in[4];
    const int* lgd = (const int*)d_in[5];
    const float* nqW = (const float*)d_in[6];  const float* nqb = (const float*)d_in[7];
    const float* nkW = (const float*)d_in[8];  const float* nkb = (const float*)d_in[9];
    const float* nvW = (const float*)d_in[10]; const float* nvb = (const float*)d_in[11];
    const float* eqW = (const float*)d_in[12]; const float* eqb = (const float*)d_in[13];
    const float* ekW = (const float*)d_in[14]; const float* ekb = (const float*)d_in[15];
    const float* evW = (const float*)d_in[16]; const float* evb = (const float*)d_in[17];
    float* out = (float*)d_out;

    cudaMemsetAsync(out, 0, (size_t)out_size * sizeof(float));

    kA<<<608, 256>>>(nin, ein, nkW, nkb, ekW, ekb, nvW, nvb, evW, evb,
                     nqW, eqW, nqb, eqb, src, dst, lgs, lgd);
    kD<<<576, 256>>>(src, dst, lgs, lgd, out);
}

// round 12
// speedup vs baseline: 1.4087x; 1.0013x over previous
#include <cuda_runtime.h>

#define NN   3072
#define EE   3072
#define ELG  6144
#define FF   64
#define HH   4
#define RPH  768        // input rows per head after .view scramble
#define TABH 9437184    // 3072*3072, lg keys offset by this

// -------- scratch (__device__ globals; no allocations allowed) --------
__device__ float g_NV[NN * 256];            // layout [n][h*64+f]
__device__ float g_EV[EE * 256];            // layout [e][h*64+f]
__device__ float g_srkp[2 * 48 * 4 * 64];   // partial srk sums [g][chunk][h][f]
__device__ float g_WT[2 * 256 * 64];        // transposed Wq (node, edge)
__device__ float g_att[2 * 4 * 3072];       // g=0: node att, g=1: edge att
__device__ float g_logit[8 * 3072];         // raw logits per (g,h)
__device__ float g_pmax[48];                // per-(gh,chunk) partial max
__device__ int   g_cnt[8];                  // softmax arrival counters (zero invariant)
__device__ int   c_srk, c_wt, c_tab;        // role-completion counters (zero invariant)
__device__ unsigned char g_winN[EE];
__device__ unsigned char g_winL[ELG];
__device__ int g_tab[2 * TABH];             // dedup tournament table (zero invariant)

// packed f32x2 helpers (FFMA2 path — ptxas never emits this from plain C++)
__device__ __forceinline__ unsigned long long pk2(float w) {
    unsigned long long r;
    asm("mov.b64 %0, {%1, %1};" : "=l"(r) : "f"(w));
    return r;
}
__device__ __forceinline__ void ffma2(unsigned long long& d,
                                      unsigned long long a, unsigned long long b) {
    asm("fma.rn.f32x2 %0, %1, %2, %0;" : "+l"(d) : "l"(a), "l"(b));
}
__device__ __forceinline__ void unpk2(unsigned long long v, float& lo, float& hi) {
    asm("mov.b64 {%0, %1}, %2;" : "=f"(lo), "=f"(hi) : "l"(v));
}

__device__ __forceinline__ void spin_until(volatile int* ctr, int target) {
    // called by thread 0 only; acquire fence after
    while (*ctr != target) {}
    __threadfence();
}

// ============ kernel A: everything except the final scatter ============
// roles by blockIdx.x (producers get lowest bids -> wave 1):
//   [0,96)      srk partials (fused K projection)        -> c_srk
//   [96,104)    transpose Wq                             -> c_wt
//   [104,140)   dedup atomicMax tournament               -> c_tab
//   [140,524)   V gemms: 64x64 tiles (NV 192, EV 192), permuted store
//   [524,572)   kBC workers (spin on c_srk,c_wt): logits + last-block softmax
//   [572,608)   winner readers (spin on c_tab)
__global__ void __launch_bounds__(256, 4) kA(
    const float* nin, const float* ein,
    const float* nkW, const float* nkb, const float* ekW, const float* ekb,
    const float* nvW, const float* nvb, const float* evW, const float* evb,
    const float* nqW, const float* eqW, const float* nqb, const float* eqb,
    const int* src, const int* dst, const int* lgs, const int* lgd)
{
    __shared__ __align__(16) float sm[8704];   // big staging union (34.8KB)
    __shared__ float s_srk[64];
    __shared__ __align__(16) float s_c[4 * 68];
    __shared__ float s_d[4];
    __shared__ float s_red[8];
    __shared__ float s_v;
    __shared__ int s_last;
    int b = blockIdx.x, tid = threadIdx.x;

    if (b < 96) {
        // ---- srk role: chunk of 64 nodes (16 KM rows per head) ----
        int g = b / 48, chunk = b % 48;
        const float* in = g ? ein : nin;
        const float* W  = g ? ekW : nkW;
        const float* bk = g ? ekb : nkb;
        float* s_in4 = sm;           // 4 heads * 16 rows * stride 68 = 4352
        float* s_wT  = sm + 4352;    // 4 * 68
        float* s_km  = sm + 4624;    // 4 * 64

        {   // vectorized fill
            const float4* in4g = (const float4*)in;
            int rr = tid >> 4, k4 = tid & 15;
            #pragma unroll
            for (int h2 = 0; h2 < 4; h2++)
                *(float4*)&s_in4[h2 * 1088 + rr * 68 + k4 * 4] =
                    in4g[(h2 * RPH + chunk * 16 + rr) * 16 + k4];
        }
        {   // transpose tiny K weights
            int k = tid >> 2, c = tid & 3;
            s_wT[c * 68 + k] = W[tid];
        }
        __syncthreads();
        int h = tid >> 6, idx = tid & 63;
        int rl = idx >> 2, c = idx & 3;
        float acc = bk[c];
        const float4* arow = (const float4*)&s_in4[h * 1088 + rl * 68];
        const float4* wrow = (const float4*)&s_wT[c * 68];
        #pragma unroll
        for (int k4 = 0; k4 < 16; k4++) {
            float4 a = arow[k4], w = wrow[k4];
            acc += a.x * w.x + a.y * w.y + a.z * w.z + a.w * w.w;
        }
        s_km[h * 64 + rl * 4 + c] = acc;
        __syncthreads();
        int f = tid & 63;
        float sacc = 0.f;
        int n0 = chunk * 64;
        #pragma unroll 8
        for (int nl = 0; nl < 64; nl++)
            sacc += in[(n0 + nl) * 64 + f] * s_km[h * 64 + nl];
        g_srkp[((g * 48 + chunk) * 4 + h) * 64 + f] = sacc;
        __threadfence();
        __syncthreads();
        if (tid == 0) atomicAdd(&c_srk, 1);

    } else if (b < 104) {
        // ---- transpose Wq: [64k][256c] -> WT[256c][64k] ----
        int t = b - 96;
        int mat = t >> 2, tile = t & 3;
        const float* W = mat ? eqW : nqW;
        float* s = sm;
        #pragma unroll
        for (int i = 0; i < 16; i++) {
            int idx = i * 256 + tid;
            int k = idx >> 6, c = idx & 63;
            s[k * 65 + c] = W[k * 256 + tile * 64 + c];
        }
        __syncthreads();
        #pragma unroll
        for (int i = 0; i < 16; i++) {
            int idx = i * 256 + tid;
            int c = idx >> 6, k = idx & 63;
            g_WT[mat * 16384 + (tile * 64 + c) * 64 + k] = s[k * 65 + c];
        }
        __threadfence();
        __syncthreads();
        if (tid == 0) atomicAdd(&c_wt, 1);

    } else if (b < 140) {
        // ---- dedup tournament: atomicMax(tab[key], e+1) ----
        int e = (b - 104) * 256 + tid;
        if (e < EE) {
            atomicMax(&g_tab[src[e] * 3072 + dst[e]], e + 1);
        } else {
            int l = e - EE;
            atomicMax(&g_tab[TABH + lgs[l] * 3072 + lgd[l]], l + 1);
        }
        __threadfence();
        __syncthreads();
        if (tid == 0) atomicAdd(&c_tab, 1);

    } else if (b < 524) {
        // ---- V gemm role: [3072x64] @ [64x256] + bias, f32x2-packed ----
        // store permuted to [n][h*64+f] for contiguous per-edge gathers in kD
        int i2 = b - 140;
        int mat = i2 / 192;
        int rem = i2 % 192;
        int r0 = (rem >> 2) * 64, c0 = (rem & 3) * 64;
        const float* in = mat ? ein : nin;
        const float* W  = mat ? evW : nvW;
        const float* bb = mat ? evb : nvb;
        float* outv     = mat ? g_EV : g_NV;
        float* As = sm;                  // 64 k * stride 68 = 4352
        float* Ws = sm + 4352;           // 64*64
        float* Bs = sm + 8448;           // 64

        #pragma unroll
        for (int i = 0; i < 16; i++) {   // A tile, transposed store (k-major)
            int idx = i * 256 + tid;
            int r = idx >> 6, k = idx & 63;
            As[k * 68 + r] = in[r0 * 64 + idx];
        }
        #pragma unroll
        for (int i = 0; i < 4; i++) {    // W tile, vectorized copy
            int idx = i * 256 + tid;
            int k = idx >> 4, c4 = idx & 15;
            *(float4*)&Ws[k * 64 + c4 * 4] =
                *(const float4*)&W[k * 256 + c0 + c4 * 4];
        }
        if (tid < 64) Bs[tid] = bb[c0 + tid];
        __syncthreads();

        int tx = tid & 15, ty = tid >> 4;
        int rl = ty * 4, cl = tx * 4;
        unsigned long long acc2[2][4];
        #pragma unroll
        for (int j = 0; j < 4; j++) {
            unsigned long long p = pk2(Bs[cl + j]);
            acc2[0][j] = p; acc2[1][j] = p;
        }

        #pragma unroll 16
        for (int k = 0; k < 64; k++) {
            ulonglong2 a = *(const ulonglong2*)&As[k * 68 + rl];
            float4 w = *(const float4*)&Ws[k * 64 + cl];
            unsigned long long wx = pk2(w.x), wy = pk2(w.y),
                               wz = pk2(w.z), ww = pk2(w.w);
            ffma2(acc2[0][0], a.x, wx); ffma2(acc2[1][0], a.y, wx);
            ffma2(acc2[0][1], a.x, wy); ffma2(acc2[1][1], a.y, wy);
            ffma2(acc2[0][2], a.x, wz); ffma2(acc2[1][2], a.y, wz);
            ffma2(acc2[0][3], a.x, ww); ffma2(acc2[1][3], a.y, ww);
        }
        // permuted store: GEMM (row, col) -> [nn][hB*64 + col%64]
        // hB = row/768 (constant per block), nn = (row%768)*4 + col/64
        int hB = r0 / 768;
        int nnb = (r0 - hB * 768 + rl) * 4 + (c0 >> 6);  // nn for local row rl, +4/row
        #pragma unroll
        for (int p = 0; p < 2; p++) {
            float lo[4], hi[4];
            #pragma unroll
            for (int j = 0; j < 4; j++) unpk2(acc2[p][j], lo[j], hi[j]);
            *(float4*)&outv[(nnb + (2 * p)     * 4) * 256 + hB * 64 + cl] =
                make_float4(lo[0], lo[1], lo[2], lo[3]);
            *(float4*)&outv[(nnb + (2 * p + 1) * 4) * 256 + hB * 64 + cl] =
                make_float4(hi[0], hi[1], hi[2], hi[3]);
        }

    } else if (b < 572) {
        // ---- kBC worker: (gh, chunk) logits + last-block softmax ----
        int w = b - 524;
        int gh = w / 6, chunk = w % 6;
        int g = gh >> 2, h = gh & 3;
        const float* in = g ? ein : nin;

        if (tid == 0) {
            spin_until(&c_srk, 96);
            spin_until(&c_wt, 8);
        }
        __syncthreads();

        // phase 1: reduce srk partials (48 chunks), scratch = sm
        {
            int f = tid & 63, p = tid >> 6;    // 4 groups x 12 chunks
            float a = 0.f;
            #pragma unroll
            for (int q = 0; q < 12; q++)
                a += g_srkp[((g * 48 + p * 12 + q) * 4 + h) * 64 + f];
            sm[tid] = a;
        }
        __syncthreads();
        if (tid < 64)
            s_srk[tid] = sm[tid] + sm[64 + tid] + sm[128 + tid] + sm[192 + tid];
        __syncthreads();

        // phase 2: c[j][k], d[j]
        {
            int j = tid & 3, k = tid >> 2;
            const float* wt = g_WT + g * 16384 + j * 4096;
            float a = 0.f;
            #pragma unroll 16
            for (int f = 0; f < 64; f++)
                a += wt[f * 64 + k] * s_srk[f];
            s_c[j * 68 + k] = a;
        }
        if (tid < 4) {
            const float* bq = g ? eqb : nqb;
            float dd = 0.f;
            #pragma unroll 16
            for (int f = 0; f < 64; f++) dd += bq[tid * 64 + f] * s_srk[f];
            s_d[tid] = dd;
        }
        __syncthreads();

        // phase 3: logits for this 128-row chunk (512 positions, 2/thread)
        {
            const float4* src4 =
                (const float4*)(in + (size_t)(h * RPH + chunk * 128) * 64);
            #pragma unroll
            for (int i = 0; i < 8; i++) {
                int idx = i * 256 + tid;
                int r = idx >> 4, k4 = idx & 15;
                *(float4*)&sm[r * 68 + k4 * 4] = src4[idx];
            }
        }
        __syncthreads();
        float lmax = -1e30f;
        #pragma unroll
        for (int it = 0; it < 2; it++) {
            int pos = it * 256 + tid;
            int ml = pos >> 2, jj = pos & 3;
            const float4* row = (const float4*)&sm[ml * 68];
            const float4* cj  = (const float4*)&s_c[jj * 68];
            float a0 = 0.f, a1 = 0.f, a2 = 0.f, a3 = 0.f;
            #pragma unroll
            for (int k = 0; k < 16; k += 4) {
                float4 r0 = row[k + 0], c0 = cj[k + 0];
                float4 r1 = row[k + 1], c1 = cj[k + 1];
                float4 r2 = row[k + 2], c2 = cj[k + 2];
                float4 r3 = row[k + 3], c3 = cj[k + 3];
                a0 += r0.x * c0.x + r0.y * c0.y + r0.z * c0.z + r0.w * c0.w;
                a1 += r1.x * c1.x + r1.y * c1.y + r1.z * c1.z + r1.w * c1.w;
                a2 += r2.x * c2.x + r2.y * c2.y + r2.z * c2.z + r2.w * c2.w;
                a3 += r3.x * c3.x + r3.y * c3.y + r3.z * c3.z + r3.w * c3.w;
            }
            float x = (s_d[jj] + ((a0 + a1) + (a2 + a3))) * 0.125f;
            g_logit[gh * 3072 + chunk * 512 + pos] = x;
            lmax = fmaxf(lmax, x);
        }
        #pragma unroll
        for (int o = 16; o > 0; o >>= 1)
            lmax = fmaxf(lmax, __shfl_xor_sync(0xffffffffu, lmax, o));
        if ((tid & 31) == 0) s_red[tid >> 5] = lmax;
        __syncthreads();
        if (tid == 0) {
            float m2 = s_red[0];
            #pragma unroll
            for (int i = 1; i < 8; i++) m2 = fmaxf(m2, s_red[i]);
            g_pmax[w] = m2;
        }
        __threadfence();
        __syncthreads();
        if (tid == 0) {
            int old = atomicAdd(&g_cnt[gh], 1);
            s_last = (old == 5);
        }
        __syncthreads();
        if (!s_last) return;
        __threadfence();

        // last arriver: softmax over all 3072 logits of this gh
        float mx = -1e30f;
        #pragma unroll
        for (int c = 0; c < 6; c++) mx = fmaxf(mx, g_pmax[gh * 6 + c]);
        const float* lg = g_logit + gh * 3072;
        float* att = g_att + gh * 3072;
        float lsum = 0.f;
        #pragma unroll
        for (int i = 0; i < 12; i++) {
            float e = __expf(lg[i * 256 + tid] - mx);
            att[i * 256 + tid] = e;
            lsum += e;
        }
        #pragma unroll
        for (int o = 16; o > 0; o >>= 1)
            lsum += __shfl_xor_sync(0xffffffffu, lsum, o);
        if ((tid & 31) == 0) s_red[tid >> 5] = lsum;
        __syncthreads();
        if (tid == 0) {
            float s = 0.f;
            #pragma unroll
            for (int i = 0; i < 8; i++) s += s_red[i];
            s_v = 1.f / s;
            g_cnt[gh] = 0;             // restore counter invariant
        }
        __syncthreads();
        float inv = s_v;
        #pragma unroll
        for (int i = 0; i < 12; i++)
            att[i * 256 + tid] *= inv;

    } else {
        // ---- winner readers: spin on tab completion ----
        if (tid == 0) spin_until(&c_tab, 36);
        __syncthreads();
        int idx = (b - 572) * 256 + tid;
        if (idx < EE) {
            g_winN[idx] = (g_tab[src[idx] * 3072 + dst[idx]] == idx + 1);
        } else {
            int l = idx - EE;
            g_winL[l] = (g_tab[TABH + lgs[l] * 3072 + lgd[l]] == l + 1);
        }
    }
}

// ======= kernel D: message-passing scatter (16 lanes/edge, float4 atomics) =======
// Loads are UNCONDITIONAL (max MLP); winner flag gates only the atomicAdd.
// blocks 0-35 also reset the tournament table; block 36 resets role counters
__global__ void __launch_bounds__(256) kD(
    const int* src, const int* dst, const int* lgs, const int* lgd, float* out)
{
    int tid = threadIdx.x;
    int bx = blockIdx.x;

    if (bx < 36) {
        int e = bx * 256 + tid;
        if (e < EE) g_tab[src[e] * 3072 + dst[e]] = 0;
        else {
            int l = e - EE;
            g_tab[TABH + lgs[l] * 3072 + lgd[l]] = 0;
        }
    } else if (bx == 36 && tid < 3) {
        if (tid == 0) c_srk = 0;
        else if (tid == 1) c_wt = 0;
        else c_tab = 0;
    }

    int u = tid >> 4;            // 16 edges per block
    int q = (tid & 15) * 4;      // float4 lane within feature dim
    if (bx < 192) {                                    // node messages (edge att, g=1)
        int e = bx * 16 + u;
        int s = src[e], d = dst[e];
        unsigned char win = g_winN[e];
        float4 acc = make_float4(0.f, 0.f, 0.f, 0.f);
        #pragma unroll
        for (int h = 0; h < 4; h++) {
            float a = __ldg(&g_att[(4 + h) * 3072 + e]);
            float4 v = *(const float4*)&g_NV[d * 256 + h * 64 + q];
            acc.x += a * v.x; acc.y += a * v.y; acc.z += a * v.z; acc.w += a * v.w;
        }
        if (!win) return;
        acc.x *= 0.25f; acc.y *= 0.25f; acc.z *= 0.25f; acc.w *= 0.25f;
        atomicAdd((float4*)&out[s * 64 + q], acc);     // mean over heads
    } else {                                           // line-graph messages (node att, g=0)
        int l = (bx - 192) * 16 + u;
        int e1 = lgs[l], e2 = lgd[l];
        int c = dst[e1];
        unsigned char win = g_winL[l];
        float4 acc = make_float4(0.f, 0.f, 0.f, 0.f);
        #pragma unroll
        for (int h = 0; h < 4; h++) {
            float a = __ldg(&g_att[h * 3072 + c]);
            float4 v = *(const float4*)&g_EV[e2 * 256 + h * 64 + q];
            acc.x += a * v.x; acc.y += a * v.y; acc.z += a * v.z; acc.w += a * v.w;
        }
        if (!win) return;
        acc.x *= 0.25f; acc.y *= 0.25f; acc.z *= 0.25f; acc.w *= 0.25f;
        atomicAdd((float4*)&out[NN * 64 + e1 * 64 + q], acc);
    }
}

extern "C" void kernel_launch(void* const* d_in, const int* in_sizes, int n_in,
                              void* d_out, int out_size)
{
    const float* nin = (const float*)d_in[0];
    const float* ein = (const float*)d_in[1];
    const int* src = (const int*)d_in[2];
    const int* dst = (const int*)d_in[3];
    const int* lgs = (const int*)d_in[4];
    const int* lgd = (const int*)d_in[5];
    const float* nqW = (const float*)d_in[6];  const float* nqb = (const float*)d_in[7];
    const float* nkW = (const float*)d_in[8];  const float* nkb = (const float*)d_in[9];
    const float* nvW = (const float*)d_in[10]; const float* nvb = (const float*)d_in[11];
    const float* eqW = (const float*)d_in[12]; const float* eqb = (const float*)d_in[13];
    const float* ekW = (const float*)d_in[14]; const float* ekb = (const float*)d_in[15];
    const float* evW = (const float*)d_in[16]; const float* evb = (const float*)d_in[17];
    float* out = (float*)d_out;

    cudaMemsetAsync(out, 0, (size_t)out_size * sizeof(float));

    kA<<<608, 256>>>(nin, ein, nkW, nkb, ekW, ekb, nvW, nvb, evW, evb,
                     nqW, eqW, nqb, eqb, src, dst, lgs, lgd);
    kD<<<576, 256>>>(src, dst, lgs, lgd, out);
}